// round 16
// baseline (speedup 1.0000x reference)
#include <cuda_runtime.h>
#include <cuda_fp16.h>
#include <cstdint>
#include <cstddef>

typedef unsigned long long ull;

#define T_LEN 2048
#define B_SZ  128
#define HID   64
#define G3    192
#define NCLS  20
#define VOCAB 50257
#define TPAD  (T_LEN + 32)

// per-vocab input projections WITH folded biases:
//   g_proj[v][d*192+g] = emb[v].wih_d[g] + bih_d[g] + (g<128 ? bhh_d[g] : 0)
__device__ float g_proj[(size_t)VOCAB * 384];
// pre-scaled, pre-reversed, padded token offsets: tok*384 + d*192
__device__ int g_tokoff[2 * B_SZ * TPAD];
// pooled features [b][256] = [mean_f, mean_b, max_f, max_b]
__device__ float g_feats[B_SZ * 256];

// ---------- fast-math helpers ----------
__device__ __forceinline__ float tanha(float x) {
    float r; asm("tanh.approx.f32 %0, %1;" : "=f"(r) : "f"(x)); return r;
}
// sigmoid via single-MUFU tanh: sigma(x) = 0.5 + 0.5*tanh(x/2)
__device__ __forceinline__ float sigm_t(float p) {
    return fmaf(tanha(0.5f * p), 0.5f, 0.5f);
}

// =====================================================================
// Kernel T: token offset table. [d][b][t] = tokens[b][TIDX(t)]*384 + d*192
// =====================================================================
__global__ void kT(const int* __restrict__ tokens) {
    const int b = blockIdx.x, d = blockIdx.y;
    const int* src = tokens + b * T_LEN;
    int* dst = g_tokoff + (d * B_SZ + b) * TPAD;
    for (int t = threadIdx.x; t < TPAD; t += blockDim.x) {
        int tt = t < T_LEN ? t : T_LEN - 1;
        int idx = d ? (T_LEN - 1 - tt) : tt;
        dst[t] = src[idx] * 384 + d * 192;
    }
}

// =====================================================================
// Kernel A2 v8: fp16 HFMA2 vocab projection, LDS.64 two-k2 loads.
// After the fp16 switch the hot loop was LDS-crossbar-bound
// (14 LDS.32 x 4 warps/SMSP = 56 cyc > 48 HFMA2 slots). This version
// processes 2 k2 per iteration via LDS.64:
//   x: xsh[v][k2] rows contiguous -> uint2 covers (k2, k2+1)
//   w: wsh[g][k2] rows padded to 34 half2 (136 B):
//      bounds: writes/reads index <= 31 < 34 (r9/r10 lesson);
//      136 B = 17*8 -> 8B-aligned LDS.64; lane stride 34 words ->
//      banks {2i,2i+1} per 16-lane phase = conflict-free.
// Accumulation order (k2 even->chain0, odd->chain1) identical to v7
// -> bit-identical numerics. 7 LDS.64 + 24 HFMA2 per 2-k2 iter.
// =====================================================================
__global__ void __launch_bounds__(256) kA2(
    const float* __restrict__ emb,
    const float* __restrict__ wih_f, const float* __restrict__ bih_f,
    const float* __restrict__ bhh_f,
    const float* __restrict__ wih_b, const float* __restrict__ bih_b,
    const float* __restrict__ bhh_b)
{
    __shared__ __half2 xsh[64][32];   // [v_local][k2]  (8 KB), rows 128 B
    __shared__ __half2 wsh[96][34];   // [g_local][k2<32] pad 34 (12.75 KB)
    __shared__ float   bsh[96];

    const int vt  = blockIdx.x;
    const int dg0 = blockIdx.y * 96;
    const int tid = threadIdx.x;

    // stage weights as half2: wsh[g][k2] = (w[dg][2k2], w[dg][2k2+1])
    for (int idx = tid; idx < 96 * 32; idx += 256) {
        int g = idx >> 5, k2 = idx & 31;
        int dg = dg0 + g;
        const float2* src = (dg < 192) ? (const float2*)(wih_f + dg * 64)
                                       : (const float2*)(wih_b + (dg - 192) * 64);
        wsh[g][k2] = __float22half2_rn(src[k2]);
    }
    if (tid < 96) {
        int dg = dg0 + tid;
        float bv;
        if (dg < 192) bv = bih_f[dg] + (dg < 128 ? bhh_f[dg] : 0.0f);
        else { int e = dg - 192; bv = bih_b[e] + (e < 128 ? bhh_b[e] : 0.0f); }
        bsh[tid] = bv;
    }
    for (int idx = tid; idx < 64 * 32; idx += 256) {
        int vl = idx >> 5, k2 = idx & 31;
        int v = vt * 64 + vl; if (v >= VOCAB) v = VOCAB - 1;
        xsh[vl][k2] = __float22half2_rn(((const float2*)(emb + (size_t)v * 64))[k2]);
    }
    __syncthreads();

    const int lane = tid & 31;
    const int wrp  = tid >> 5;
    const __half2 z2 = __float2half2_rn(0.0f);

#pragma unroll
    for (int pass = 0; pass < 2; pass++) {
        const int row0 = pass * 32 + wrp * 4;

        // two fp16 chains per output (k2 parity), 16 deep each
        __half2 acc[4][3][2];
#pragma unroll
        for (int i = 0; i < 4; i++)
#pragma unroll
            for (int q = 0; q < 3; q++) { acc[i][q][0] = z2; acc[i][q][1] = z2; }

#pragma unroll 4
        for (int kk = 0; kk < 16; kk++) {
            // x pairs: broadcast LDS.64 per row (k2 = 2kk, 2kk+1)
            uint2 xv[4];
#pragma unroll
            for (int i = 0; i < 4; i++)
                xv[i] = *(const uint2*)&xsh[row0 + i][2 * kk];
            // w pairs: coalesced conflict-free LDS.64
            uint2 wv[3];
#pragma unroll
            for (int q = 0; q < 3; q++)
                wv[q] = *(const uint2*)&wsh[lane + 32 * q][2 * kk];

#pragma unroll
            for (int i = 0; i < 4; i++) {
                const __half2 x0 = *(const __half2*)&xv[i].x;
                const __half2 x1 = *(const __half2*)&xv[i].y;
#pragma unroll
                for (int q = 0; q < 3; q++) {
                    const __half2 w0 = *(const __half2*)&wv[q].x;
                    const __half2 w1 = *(const __half2*)&wv[q].y;
                    acc[i][q][0] = __hfma2(x0, w0, acc[i][q][0]);
                    acc[i][q][1] = __hfma2(x1, w1, acc[i][q][1]);
                }
            }
        }

#pragma unroll
        for (int i = 0; i < 4; i++) {
            int v = vt * 64 + row0 + i;
            if (v < VOCAB) {
#pragma unroll
                for (int q = 0; q < 3; q++) {
                    int g = lane + 32 * q;
                    float2 c0 = __half22float2(acc[i][q][0]);
                    float2 c1 = __half22float2(acc[i][q][1]);
                    g_proj[(size_t)v * 384 + dg0 + g] =
                        (c0.x + c0.y) + (c1.x + c1.y) + bsh[g];
                }
            }
        }
    }
}

// =====================================================================
// Kernel B v14 (FROZEN, proven r15 = 523.9us): fp16 HFMA2 recurrent dot,
// hadd2 chain-combine + symmetric 0.5*bn fold.
// 256 CTAs = one (d,b) sequence, 128 threads: k = tid>>1, half = tid&1.
// =====================================================================
__global__ void __launch_bounds__(128) kB(
    const float* __restrict__ whh_f, const float* __restrict__ bhh_f,
    const float* __restrict__ whh_b, const float* __restrict__ bhh_b)
{
    __shared__ __align__(16) __half h_sh[2][64];   // [buf][k]

    const int tid  = threadIdx.x;
    const int k    = tid >> 1;
    const int half = tid & 1;
    const int d    = blockIdx.x >> 7;
    const int b    = blockIdx.x & 127;

    const float* whh = d ? whh_b : whh_f;
    const float* bhh = d ? bhh_b : bhh_f;

    // fp16x2 register-resident weight halves (cols [half*32, half*32+32))
    __half2 wr[16], wz[16], wn[16];
    {
        const float2* prp = (const float2*)(whh + (size_t)k * 64         + half * 32);
        const float2* pzp = (const float2*)(whh + (size_t)(64 + k) * 64  + half * 32);
        const float2* pnp = (const float2*)(whh + (size_t)(128 + k) * 64 + half * 32);
#pragma unroll
        for (int i = 0; i < 16; i++) {
            wr[i] = __float22half2_rn(prp[i]);
            wz[i] = __float22half2_rn(pzp[i]);
            wn[i] = __float22half2_rn(pnp[i]);
        }
    }
    const float bn_half = 0.5f * bhh[128 + k];   // symmetric fold, no select

    if (tid < 64) h_sh[0][tid] = __float2half(0.0f);

    const int4* tq = (const int4*)(g_tokoff + (d * B_SZ + b) * TPAD);
    const float* pA = g_proj + (half ? 64 : 0) + k;  // xr (half0) / xz (half1)
    const float* pB = g_proj + 128 + k;              // xn (both halves)

    int4 q0 = tq[0], q1 = tq[1], q2 = tq[2], q3 = tq[3];

    float bufA[8], bufB[8];
    bufA[0] = pA[q0.x]; bufB[0] = pB[q0.x];
    bufA[1] = pA[q0.y]; bufB[1] = pB[q0.y];
    bufA[2] = pA[q0.z]; bufB[2] = pB[q0.z];
    bufA[3] = pA[q0.w]; bufB[3] = pB[q0.w];
    bufA[4] = pA[q1.x]; bufB[4] = pB[q1.x];
    bufA[5] = pA[q1.y]; bufB[5] = pB[q1.y];
    bufA[6] = pA[q1.z]; bufB[6] = pB[q1.z];
    bufA[7] = pA[q1.w]; bufB[7] = pB[q1.w];

    float hprev = 0.0f, sum = 0.0f, mx = -1e30f;
    __syncthreads();

    const __half2 z2 = __float2half2_rn(0.0f);

    for (int t0 = 0; t0 < T_LEN; t0 += 8) {
        int4 qn0, qn1;
#pragma unroll
        for (int j = 0; j < 8; j++) {
            const int cur = j & 1;

            const float a0 = bufA[j];       // xr+b (half0) / xz+b (half1)
            const float b0 = bufB[j];       // xn+bih_n
            if (j == 0) qn0 = tq[(t0 + 16) >> 2];
            if (j == 4) qn1 = tq[(t0 + 20) >> 2];
            {
                const int voj = (j == 0) ? q2.x : (j == 1) ? q2.y : (j == 2) ? q2.z :
                                (j == 3) ? q2.w : (j == 4) ? q3.x : (j == 5) ? q3.y :
                                (j == 6) ? q3.z : q3.w;
                bufA[j] = pA[voj];
                bufB[j] = pB[voj];
            }

            // load 32 h halves (this thread's column slice) = 16 half2
            __half2 hv[16];
            {
                const uint4* hp = (const uint4*)&h_sh[cur][half * 32];
                uint4 u0 = hp[0], u1 = hp[1], u2 = hp[2], u3 = hp[3];
                ((uint4*)hv)[0] = u0; ((uint4*)hv)[1] = u1;
                ((uint4*)hv)[2] = u2; ((uint4*)hv)[3] = u3;
            }

            // fp16 half-dot: 2 accumulation chains per gate row
            __half2 ar0 = z2, ar1 = z2, az0 = z2, az1 = z2, an0 = z2, an1 = z2;
#pragma unroll
            for (int i = 0; i < 8; i++) {
                ar0 = __hfma2(wr[2 * i], hv[2 * i], ar0);
                ar1 = __hfma2(wr[2 * i + 1], hv[2 * i + 1], ar1);
                az0 = __hfma2(wz[2 * i], hv[2 * i], az0);
                az1 = __hfma2(wz[2 * i + 1], hv[2 * i + 1], az1);
                an0 = __hfma2(wn[2 * i], hv[2 * i], an0);
                an1 = __hfma2(wn[2 * i + 1], hv[2 * i + 1], an1);
            }
            // hadd2 combine + fp32 finish
            float2 fr = __half22float2(__hadd2(ar0, ar1));
            float2 fz = __half22float2(__hadd2(az0, az1));
            float2 fn = __half22float2(__hadd2(an0, an1));
            float pr = fr.x + fr.y + (half ? 0.0f : a0);
            float pz = fz.x + fz.y + (half ? a0 : 0.0f);
            float pn = fn.x + fn.y + bn_half;   // both halves add bn/2
            pr += __shfl_xor_sync(0xffffffffu, pr, 1);
            pz += __shfl_xor_sync(0xffffffffu, pz, 1);
            pn += __shfl_xor_sync(0xffffffffu, pn, 1);

            const float R  = sigm_t(pr);
            const float Z  = sigm_t(pz);
            const float N  = tanha(fmaf(R, pn, b0));
            const float hn = fmaf(Z, hprev - N, N);     // (1-z)n + z h
            hprev = hn;
            if (half == 0) h_sh[cur ^ 1][k] = __float2half(hn);
            sum += hn;
            mx = fmaxf(mx, hn);

            __syncthreads();
        }
        q2 = qn0; q3 = qn1;
    }

    if (half == 0) {
        float* f = g_feats + b * 256;
        if (d == 0) { f[k]      = sum * (1.0f / T_LEN); f[128 + k] = mx; }
        else        { f[64 + k] = sum * (1.0f / T_LEN); f[192 + k] = mx; }
    }
}

// =====================================================================
// Kernel C v2 (FROZEN): classifier head, 256 threads per batch row.
// =====================================================================
__global__ void __launch_bounds__(256) kC(
    const float* __restrict__ w1, const float* __restrict__ b1,
    const float* __restrict__ w2, const float* __restrict__ b2,
    float* __restrict__ out)
{
    const int b   = blockIdx.x;
    const int tid = threadIdx.x;
    __shared__ float hid[64];

    {
        const int j = tid >> 2, q = tid & 3;
        const float4* f4 = (const float4*)(g_feats + b * 256 + q * 64);
        const float4* w4 = (const float4*)(w1 + j * 256 + q * 64);
        float a0 = 0.f, a1 = 0.f, a2 = 0.f, a3 = 0.f;
#pragma unroll
        for (int i = 0; i < 16; i += 4) {
            float4 fa = f4[i],     wa = w4[i];
            float4 fb = f4[i + 1], wb = w4[i + 1];
            float4 fc = f4[i + 2], wc = w4[i + 2];
            float4 fd = f4[i + 3], wd = w4[i + 3];
            a0 += fa.x * wa.x + fa.y * wa.y + fa.z * wa.z + fa.w * wa.w;
            a1 += fb.x * wb.x + fb.y * wb.y + fb.z * wb.z + fb.w * wb.w;
            a2 += fc.x * wc.x + fc.y * wc.y + fc.z * wc.z + fc.w * wc.w;
            a3 += fd.x * wd.x + fd.y * wd.y + fd.z * wd.z + fd.w * wd.w;
        }
        float acc = (a0 + a1) + (a2 + a3);
        acc += __shfl_xor_sync(0xffffffffu, acc, 1);
        acc += __shfl_xor_sync(0xffffffffu, acc, 2);
        if (q == 0) {
            acc += b1[j];
            hid[j] = 0.5f * acc * (1.0f + erff(acc * 0.70710678118654752f));
        }
    }
    __syncthreads();

    if (tid < NCLS * 8) {
        const int c = tid >> 3, i8 = tid & 7;
        const float* w2r = w2 + c * 64 + i8 * 8;
        const float* hp  = hid + i8 * 8;
        float o = 0.f;
#pragma unroll
        for (int i = 0; i < 8; i++) o += hp[i] * w2r[i];
        o += __shfl_xor_sync(0xffffffffu, o, 1);
        o += __shfl_xor_sync(0xffffffffu, o, 2);
        o += __shfl_xor_sync(0xffffffffu, o, 4);
        if (i8 == 0) out[b * NCLS + c] = o + b2[c];
    }
}

// =====================================================================
extern "C" void kernel_launch(void* const* d_in, const int* in_sizes, int n_in,
                              void* d_out, int out_size)
{
    const int*   tokens = (const int*)  d_in[0];
    const float* emb    = (const float*)d_in[1];
    const float* wih_f  = (const float*)d_in[2];
    const float* whh_f  = (const float*)d_in[3];
    const float* bih_f  = (const float*)d_in[4];
    const float* bhh_f  = (const float*)d_in[5];
    const float* wih_b  = (const float*)d_in[6];
    const float* whh_b  = (const float*)d_in[7];
    const float* bih_b  = (const float*)d_in[8];
    const float* bhh_b  = (const float*)d_in[9];
    const float* w1     = (const float*)d_in[10];
    const float* b1     = (const float*)d_in[11];
    const float* w2     = (const float*)d_in[12];
    const float* b2     = (const float*)d_in[13];
    float* out = (float*)d_out;

    kT<<<dim3(B_SZ, 2), 256>>>(tokens);
    const int vtiles = (VOCAB + 63) / 64;   // 786
    kA2<<<dim3(vtiles, 4), 256>>>(emb, wih_f, bih_f, bhh_f, wih_b, bih_b, bhh_b);
    kB<<<256, 128>>>(whh_f, bhh_f, whh_b, bhh_b);
    kC<<<128, 256>>>(w1, b1, w2, b2, out);
}

// round 17
// speedup vs baseline: 1.0493x; 1.0493x over previous
#include <cuda_runtime.h>
#include <cuda_fp16.h>
#include <cstdint>
#include <cstddef>

typedef unsigned long long ull;

#define T_LEN 2048
#define B_SZ  128
#define HID   64
#define G3    192
#define NCLS  20
#define VOCAB 50257
#define TPAD  (T_LEN + 32)

// per-vocab input projections WITH folded biases:
//   g_proj[v][d*192+g] = emb[v].wih_d[g] + bih_d[g] + (g<128 ? bhh_d[g] : 0)
__device__ float g_proj[(size_t)VOCAB * 384];
// pre-scaled, pre-reversed, padded token offsets: tok*384 + d*192
__device__ int g_tokoff[2 * B_SZ * TPAD];
// pooled features [b][256] = [mean_f, mean_b, max_f, max_b]
__device__ float g_feats[B_SZ * 256];

// ---------- fast-math helpers ----------
__device__ __forceinline__ float tanha(float x) {
    float r; asm("tanh.approx.f32 %0, %1;" : "=f"(r) : "f"(x)); return r;
}
// sigmoid via single-MUFU tanh: sigma(x) = 0.5 + 0.5*tanh(x/2)
__device__ __forceinline__ float sigm_t(float p) {
    return fmaf(tanha(0.5f * p), 0.5f, 0.5f);
}

// =====================================================================
// Kernel T: token offset table. [d][b][t] = tokens[b][TIDX(t)]*384 + d*192
// =====================================================================
__global__ void kT(const int* __restrict__ tokens) {
    const int b = blockIdx.x, d = blockIdx.y;
    const int* src = tokens + b * T_LEN;
    int* dst = g_tokoff + (d * B_SZ + b) * TPAD;
    for (int t = threadIdx.x; t < TPAD; t += blockDim.x) {
        int tt = t < T_LEN ? t : T_LEN - 1;
        int idx = d ? (T_LEN - 1 - tt) : tt;
        dst[t] = src[idx] * 384 + d * 192;
    }
}

// =====================================================================
// Kernel A2 v7 (PROVEN r14/r15, ~76us): fp16 HFMA2 vocab projection.
// LDS.32 broadcast/coalesced loads (the v8 LDS.64 variant regressed).
// Two 16-deep fp16 chains per output (k2 parity), fp32 combine.
// =====================================================================
__global__ void __launch_bounds__(256) kA2(
    const float* __restrict__ emb,
    const float* __restrict__ wih_f, const float* __restrict__ bih_f,
    const float* __restrict__ bhh_f,
    const float* __restrict__ wih_b, const float* __restrict__ bih_b,
    const float* __restrict__ bhh_b)
{
    __shared__ __half2 xsh[64][32];   // [v_local][k2]  (8 KB)
    __shared__ __half2 wsh[32][97];   // [k2][g_local] padded (12.1 KB)
    __shared__ float   bsh[96];

    const int vt  = blockIdx.x;
    const int dg0 = blockIdx.y * 96;
    const int tid = threadIdx.x;

    for (int idx = tid; idx < 96 * 32; idx += 256) {
        int g = idx >> 5, k2 = idx & 31;
        int dg = dg0 + g;
        const float2* src = (dg < 192) ? (const float2*)(wih_f + dg * 64)
                                       : (const float2*)(wih_b + (dg - 192) * 64);
        wsh[k2][g] = __float22half2_rn(src[k2]);
    }
    if (tid < 96) {
        int dg = dg0 + tid;
        float bv;
        if (dg < 192) bv = bih_f[dg] + (dg < 128 ? bhh_f[dg] : 0.0f);
        else { int e = dg - 192; bv = bih_b[e] + (e < 128 ? bhh_b[e] : 0.0f); }
        bsh[tid] = bv;
    }
    for (int idx = tid; idx < 64 * 32; idx += 256) {
        int vl = idx >> 5, k2 = idx & 31;
        int v = vt * 64 + vl; if (v >= VOCAB) v = VOCAB - 1;
        xsh[vl][k2] = __float22half2_rn(((const float2*)(emb + (size_t)v * 64))[k2]);
    }
    __syncthreads();

    const int lane = tid & 31;
    const int wrp  = tid >> 5;
    const __half2 z2 = __float2half2_rn(0.0f);

#pragma unroll
    for (int pass = 0; pass < 2; pass++) {
        const int row0 = pass * 32 + wrp * 4;

        __half2 acc[4][3][2];
#pragma unroll
        for (int i = 0; i < 4; i++)
#pragma unroll
            for (int q = 0; q < 3; q++) { acc[i][q][0] = z2; acc[i][q][1] = z2; }

#pragma unroll 4
        for (int k2 = 0; k2 < 32; k2++) {
            const int c = k2 & 1;
            __half2 xs[4], ws[3];
#pragma unroll
            for (int i = 0; i < 4; i++) xs[i] = xsh[row0 + i][k2];
#pragma unroll
            for (int q = 0; q < 3; q++) ws[q] = wsh[k2][lane + 32 * q];
#pragma unroll
            for (int i = 0; i < 4; i++)
#pragma unroll
                for (int q = 0; q < 3; q++)
                    acc[i][q][c] = __hfma2(xs[i], ws[q], acc[i][q][c]);
        }

#pragma unroll
        for (int i = 0; i < 4; i++) {
            int v = vt * 64 + row0 + i;
            if (v < VOCAB) {
#pragma unroll
                for (int q = 0; q < 3; q++) {
                    int g = lane + 32 * q;
                    float2 c0 = __half22float2(acc[i][q][0]);
                    float2 c1 = __half22float2(acc[i][q][1]);
                    g_proj[(size_t)v * 384 + dg0 + g] =
                        (c0.x + c0.y) + (c1.x + c1.y) + bsh[g];
                }
            }
        }
    }
}

// =====================================================================
// Kernel B v14 (PROVEN r15 = 523.9us): fp16 HFMA2 recurrent dot,
// hadd2 chain-combine + symmetric 0.5*bn fold.
// 256 CTAs = one (d,b) sequence, 128 threads: k = tid>>1, half = tid&1.
// =====================================================================
__global__ void __launch_bounds__(128) kB(
    const float* __restrict__ whh_f, const float* __restrict__ bhh_f,
    const float* __restrict__ whh_b, const float* __restrict__ bhh_b)
{
    __shared__ __align__(16) __half h_sh[2][64];   // [buf][k]

    const int tid  = threadIdx.x;
    const int k    = tid >> 1;
    const int half = tid & 1;
    const int d    = blockIdx.x >> 7;
    const int b    = blockIdx.x & 127;

    const float* whh = d ? whh_b : whh_f;
    const float* bhh = d ? bhh_b : bhh_f;

    // fp16x2 register-resident weight halves (cols [half*32, half*32+32))
    __half2 wr[16], wz[16], wn[16];
    {
        const float2* prp = (const float2*)(whh + (size_t)k * 64         + half * 32);
        const float2* pzp = (const float2*)(whh + (size_t)(64 + k) * 64  + half * 32);
        const float2* pnp = (const float2*)(whh + (size_t)(128 + k) * 64 + half * 32);
#pragma unroll
        for (int i = 0; i < 16; i++) {
            wr[i] = __float22half2_rn(prp[i]);
            wz[i] = __float22half2_rn(pzp[i]);
            wn[i] = __float22half2_rn(pnp[i]);
        }
    }
    const float bn_half = 0.5f * bhh[128 + k];   // symmetric fold, no select

    if (tid < 64) h_sh[0][tid] = __float2half(0.0f);

    const int4* tq = (const int4*)(g_tokoff + (d * B_SZ + b) * TPAD);
    const float* pA = g_proj + (half ? 64 : 0) + k;  // xr (half0) / xz (half1)
    const float* pB = g_proj + 128 + k;              // xn (both halves)

    int4 q0 = tq[0], q1 = tq[1], q2 = tq[2], q3 = tq[3];

    float bufA[8], bufB[8];
    bufA[0] = pA[q0.x]; bufB[0] = pB[q0.x];
    bufA[1] = pA[q0.y]; bufB[1] = pB[q0.y];
    bufA[2] = pA[q0.z]; bufB[2] = pB[q0.z];
    bufA[3] = pA[q0.w]; bufB[3] = pB[q0.w];
    bufA[4] = pA[q1.x]; bufB[4] = pB[q1.x];
    bufA[5] = pA[q1.y]; bufB[5] = pB[q1.y];
    bufA[6] = pA[q1.z]; bufB[6] = pB[q1.z];
    bufA[7] = pA[q1.w]; bufB[7] = pB[q1.w];

    float hprev = 0.0f, sum = 0.0f, mx = -1e30f;
    __syncthreads();

    const __half2 z2 = __float2half2_rn(0.0f);

    for (int t0 = 0; t0 < T_LEN; t0 += 8) {
        int4 qn0, qn1;
#pragma unroll
        for (int j = 0; j < 8; j++) {
            const int cur = j & 1;

            const float a0 = bufA[j];       // xr+b (half0) / xz+b (half1)
            const float b0 = bufB[j];       // xn+bih_n
            if (j == 0) qn0 = tq[(t0 + 16) >> 2];
            if (j == 4) qn1 = tq[(t0 + 20) >> 2];
            {
                const int voj = (j == 0) ? q2.x : (j == 1) ? q2.y : (j == 2) ? q2.z :
                                (j == 3) ? q2.w : (j == 4) ? q3.x : (j == 5) ? q3.y :
                                (j == 6) ? q3.z : q3.w;
                bufA[j] = pA[voj];
                bufB[j] = pB[voj];
            }

            // load 32 h halves (this thread's column slice) = 16 half2
            __half2 hv[16];
            {
                const uint4* hp = (const uint4*)&h_sh[cur][half * 32];
                uint4 u0 = hp[0], u1 = hp[1], u2 = hp[2], u3 = hp[3];
                ((uint4*)hv)[0] = u0; ((uint4*)hv)[1] = u1;
                ((uint4*)hv)[2] = u2; ((uint4*)hv)[3] = u3;
            }

            // fp16 half-dot: 2 accumulation chains per gate row
            __half2 ar0 = z2, ar1 = z2, az0 = z2, az1 = z2, an0 = z2, an1 = z2;
#pragma unroll
            for (int i = 0; i < 8; i++) {
                ar0 = __hfma2(wr[2 * i], hv[2 * i], ar0);
                ar1 = __hfma2(wr[2 * i + 1], hv[2 * i + 1], ar1);
                az0 = __hfma2(wz[2 * i], hv[2 * i], az0);
                az1 = __hfma2(wz[2 * i + 1], hv[2 * i + 1], az1);
                an0 = __hfma2(wn[2 * i], hv[2 * i], an0);
                an1 = __hfma2(wn[2 * i + 1], hv[2 * i + 1], an1);
            }
            // hadd2 combine + fp32 finish
            float2 fr = __half22float2(__hadd2(ar0, ar1));
            float2 fz = __half22float2(__hadd2(az0, az1));
            float2 fn = __half22float2(__hadd2(an0, an1));
            float pr = fr.x + fr.y + (half ? 0.0f : a0);
            float pz = fz.x + fz.y + (half ? a0 : 0.0f);
            float pn = fn.x + fn.y + bn_half;   // both halves add bn/2
            pr += __shfl_xor_sync(0xffffffffu, pr, 1);
            pz += __shfl_xor_sync(0xffffffffu, pz, 1);
            pn += __shfl_xor_sync(0xffffffffu, pn, 1);

            const float R  = sigm_t(pr);
            const float Z  = sigm_t(pz);
            const float N  = tanha(fmaf(R, pn, b0));
            const float hn = fmaf(Z, hprev - N, N);     // (1-z)n + z h
            hprev = hn;
            if (half == 0) h_sh[cur ^ 1][k] = __float2half(hn);
            sum += hn;
            mx = fmaxf(mx, hn);

            __syncthreads();
        }
        q2 = qn0; q3 = qn1;
    }

    if (half == 0) {
        float* f = g_feats + b * 256;
        if (d == 0) { f[k]      = sum * (1.0f / T_LEN); f[128 + k] = mx; }
        else        { f[64 + k] = sum * (1.0f / T_LEN); f[192 + k] = mx; }
    }
}

// =====================================================================
// Kernel C v2 (FROZEN): classifier head, 256 threads per batch row.
// =====================================================================
__global__ void __launch_bounds__(256) kC(
    const float* __restrict__ w1, const float* __restrict__ b1,
    const float* __restrict__ w2, const float* __restrict__ b2,
    float* __restrict__ out)
{
    const int b   = blockIdx.x;
    const int tid = threadIdx.x;
    __shared__ float hid[64];

    {
        const int j = tid >> 2, q = tid & 3;
        const float4* f4 = (const float4*)(g_feats + b * 256 + q * 64);
        const float4* w4 = (const float4*)(w1 + j * 256 + q * 64);
        float a0 = 0.f, a1 = 0.f, a2 = 0.f, a3 = 0.f;
#pragma unroll
        for (int i = 0; i < 16; i += 4) {
            float4 fa = f4[i],     wa = w4[i];
            float4 fb = f4[i + 1], wb = w4[i + 1];
            float4 fc = f4[i + 2], wc = w4[i + 2];
            float4 fd = f4[i + 3], wd = w4[i + 3];
            a0 += fa.x * wa.x + fa.y * wa.y + fa.z * wa.z + fa.w * wa.w;
            a1 += fb.x * wb.x + fb.y * wb.y + fb.z * wb.z + fb.w * wb.w;
            a2 += fc.x * wc.x + fc.y * wc.y + fc.z * wc.z + fc.w * wc.w;
            a3 += fd.x * wd.x + fd.y * wd.y + fd.z * wd.z + fd.w * wd.w;
        }
        float acc = (a0 + a1) + (a2 + a3);
        acc += __shfl_xor_sync(0xffffffffu, acc, 1);
        acc += __shfl_xor_sync(0xffffffffu, acc, 2);
        if (q == 0) {
            acc += b1[j];
            hid[j] = 0.5f * acc * (1.0f + erff(acc * 0.70710678118654752f));
        }
    }
    __syncthreads();

    if (tid < NCLS * 8) {
        const int c = tid >> 3, i8 = tid & 7;
        const float* w2r = w2 + c * 64 + i8 * 8;
        const float* hp  = hid + i8 * 8;
        float o = 0.f;
#pragma unroll
        for (int i = 0; i < 8; i++) o += hp[i] * w2r[i];
        o += __shfl_xor_sync(0xffffffffu, o, 1);
        o += __shfl_xor_sync(0xffffffffu, o, 2);
        o += __shfl_xor_sync(0xffffffffu, o, 4);
        if (i8 == 0) out[b * NCLS + c] = o + b2[c];
    }
}

// =====================================================================
extern "C" void kernel_launch(void* const* d_in, const int* in_sizes, int n_in,
                              void* d_out, int out_size)
{
    const int*   tokens = (const int*)  d_in[0];
    const float* emb    = (const float*)d_in[1];
    const float* wih_f  = (const float*)d_in[2];
    const float* whh_f  = (const float*)d_in[3];
    const float* bih_f  = (const float*)d_in[4];
    const float* bhh_f  = (const float*)d_in[5];
    const float* wih_b  = (const float*)d_in[6];
    const float* whh_b  = (const float*)d_in[7];
    const float* bih_b  = (const float*)d_in[8];
    const float* bhh_b  = (const float*)d_in[9];
    const float* w1     = (const float*)d_in[10];
    const float* b1     = (const float*)d_in[11];
    const float* w2     = (const float*)d_in[12];
    const float* b2     = (const float*)d_in[13];
    float* out = (float*)d_out;

    kT<<<dim3(B_SZ, 2), 256>>>(tokens);
    const int vtiles = (VOCAB + 63) / 64;   // 786
    kA2<<<dim3(vtiles, 4), 256>>>(emb, wih_f, bih_f, bhh_f, wih_b, bih_b, bhh_b);
    kB<<<256, 128>>>(whh_f, bhh_f, whh_b, bhh_b);
    kC<<<128, 256>>>(w1, b1, w2, b2, out);
}